// round 8
// baseline (speedup 1.0000x reference)
#include <cuda_runtime.h>
#include <cstdint>

#define NQ      8192
#define NR      16384
#define KNN     8
#define NCHUNK  16
#define RPC     (NR / NCHUNK)    // 1024 refs per chunk
#define PPC     (RPC / 2)        // 512 packed pairs (16 KB tile)
#define QPB     128              // threads (=queries) per block, 4 warps
#define QBLK    (NQ / QPB)       // 64 query-blocks -> grid 1024
#define NSL     16               // slices per chunk
#define PPSL    (PPC / NSL)      // 32 pairs per slice (32 sub-minima/chunk)
#define CAPP    24               // candidate cap in PAIRS per (query, chunk)

typedef unsigned long long ull;

__device__ ulonglong2 g_ckey[(size_t)NQ * NCHUNK * CAPP];   // 50 MB scratch
__device__ int        g_cnt[NQ * NCHUNK];

__device__ __forceinline__ ull fma2(ull a, ull b, ull c) {
    ull d; asm("fma.rn.f32x2 %0, %1, %2, %3;" : "=l"(d) : "l"(a), "l"(b), "l"(c));
    return d;
}
__device__ __forceinline__ ull pk2(float lo, float hi) {
    ull r; asm("mov.b64 %0, {%1, %2};" : "=l"(r) : "f"(lo), "f"(hi));
    return r;
}
__device__ __forceinline__ void up2(float& lo, float& hi, ull v) {
    asm("mov.b64 {%0, %1}, %2;" : "=f"(lo), "=f"(hi) : "l"(v));
}
__device__ __forceinline__ unsigned f2ord(float f) {
    unsigned b = __float_as_uint(f);
    return (b & 0x80000000u) ? ~b : (b | 0x80000000u);
}

// p1: block stages its chunk (packed {x01,y01,z01,w01}) in SMEM straight from
// raw ref, then: pass A = branchless sub-minima -> tau; pass C = fully
// predicated candidate-pair compaction (no branches, no divergence, no atomics).
__global__ __launch_bounds__(QPB) void knn_p1(const float* __restrict__ qry,
                                              const float* __restrict__ ref) {
    __shared__ ulonglong4 tile[PPC];          // 16 KB
    const int chunk = blockIdx.x % NCHUNK;
    const int qi    = (blockIdx.x / NCHUNK) * QPB + threadIdx.x;
    const int rbase = chunk * RPC;

    // Fused pack: 6 floats per pair, 8B-aligned float2 loads; w = r^2 with the
    // reference's rounding ((x*x + y*y) + z*z, no contraction).
    for (int p = threadIdx.x; p < PPC; p += QPB) {
        const float2* a = (const float2*)(ref + (size_t)(rbase + 2 * p) * 3);
        float2 u0 = __ldg(a), u1 = __ldg(a + 1), u2 = __ldg(a + 2);
        float x0 = u0.x, y0 = u0.y, z0 = u1.x, x1 = u1.y, y1 = u2.x, z1 = u2.y;
        float w0 = __fadd_rn(__fadd_rn(__fmul_rn(x0, x0), __fmul_rn(y0, y0)), __fmul_rn(z0, z0));
        float w1 = __fadd_rn(__fadd_rn(__fmul_rn(x1, x1), __fmul_rn(y1, y1)), __fmul_rn(z1, z1));
        ulonglong4 v;
        v.x = pk2(x0, x1); v.y = pk2(y0, y1); v.z = pk2(z0, z1); v.w = pk2(w0, w1);
        tile[p] = v;
    }

    const float qx = qry[qi * 3 + 0];
    const float qy = qry[qi * 3 + 1];
    const float qz = qry[qi * 3 + 2];
    const ull m2x = pk2(-2.0f * qx, -2.0f * qx);
    const ull m2y = pk2(-2.0f * qy, -2.0f * qy);
    const ull m2z = pk2(-2.0f * qz, -2.0f * qz);

    const float INF = __int_as_float(0x7f800000);
    __syncthreads();

    // Pass A: 32 sub-minima folded into a sorted-8 of values (pure fmin/fmax).
    float t[KNN];
#pragma unroll
    for (int j = 0; j < KNN; ++j) t[j] = INF;

    for (int sl = 0; sl < NSL; ++sl) {
        float a0 = INF, a1 = INF;
        const ulonglong4* base = tile + sl * PPSL;
#pragma unroll 8
        for (int it = 0; it < PPSL; ++it) {
            ulonglong4 v = base[it];          // warp-uniform -> LDS broadcast
            ull s2 = fma2(m2x, v.x, fma2(m2y, v.y, fma2(m2z, v.z, v.w)));
            float s0, s1; up2(s0, s1, s2);
            a0 = fminf(a0, s0); a1 = fminf(a1, s1);
        }
        float c0 = a0;
#pragma unroll
        for (int j = 0; j < KNN; ++j) { float lo = fminf(t[j], c0), hi = fmaxf(t[j], c0); t[j] = lo; c0 = hi; }
        float c1 = a1;
#pragma unroll
        for (int j = 0; j < KNN; ++j) { float lo = fminf(t[j], c1), hi = fmaxf(t[j], c1); t[j] = lo; c1 = hi; }
    }
    // tau >= this chunk's true 8th-smallest distance (8 distinct elems <= tau).
    const float tau = t[KNN - 1];

    // Pass C: fully predicated compaction. A pair is stored (both keys) iff
    // min(s0,s1) <= tau; the >tau half is just a valid far candidate (harmless).
    // Keys are raw (float_bits<<32 | idx); p2 applies the order transform.
    int c = 0;
    ulonglong2* buf = g_ckey + ((size_t)qi * NCHUNK + chunk) * CAPP;
#pragma unroll 4
    for (int p = 0; p < PPC; ++p) {
        ulonglong4 v = tile[p];
        ull s2 = fma2(m2x, v.x, fma2(m2y, v.y, fma2(m2z, v.z, v.w)));
        float s0, s1; up2(s0, s1, s2);
        unsigned ri = (unsigned)(rbase + 2 * p);
        ull k0 = ((ull)__float_as_uint(s0) << 32) | ri;
        ull k1 = ((ull)__float_as_uint(s1) << 32) | (ri + 1);
        float smin = fminf(s0, s1);
        ulonglong2* addr = buf + (c < CAPP - 1 ? c : CAPP - 1);
        asm volatile("{\n\t"
                     ".reg .pred p;\n\t"
                     "setp.le.f32 p, %0, %1;\n\t"
                     "@p st.global.v2.u64 [%2], {%3, %4};\n\t"
                     "}" :: "f"(smin), "f"(tau), "l"(addr), "l"(k0), "l"(k1)
                     : "memory");
        c += (smin <= tau);
    }
    g_cnt[qi * NCHUNK + chunk] = (c < CAPP) ? c : CAPP;
}

// p2: merge ~2*13 keys x 16 chunks per query; emit top-8 indices as floats.
__global__ void knn_p2(float* __restrict__ out) {
    int qi = blockIdx.x * blockDim.x + threadIdx.x;
    if (qi >= NQ) return;

    ull best[KNN];
#pragma unroll
    for (int j = 0; j < KNN; ++j) best[j] = ~0ull;

    for (int ch = 0; ch < NCHUNK; ++ch) {
        int n = g_cnt[qi * NCHUNK + ch];
        const ulonglong2* buf = g_ckey + ((size_t)qi * NCHUNK + ch) * CAPP;
        for (int j = 0; j < n; ++j) {
            ulonglong2 kp = buf[j];
#pragma unroll 2
            for (int h = 0; h < 2; ++h) {
                ull raw = h ? kp.y : kp.x;
                // order-transform the float high word, keep idx low word
                ull k = ((ull)f2ord(__uint_as_float((unsigned)(raw >> 32))) << 32)
                        | (raw & 0xffffffffu);
                if (k < best[KNN - 1]) {
#pragma unroll
                    for (int m = 0; m < KNN; ++m) {
                        if (k < best[m]) { ull tmp = best[m]; best[m] = k; k = tmp; }
                    }
                }
            }
        }
    }
#pragma unroll
    for (int j = 0; j < KNN; ++j)
        out[qi * KNN + j] = (float)(int)(best[j] & 0xffffffffu);
}

extern "C" void kernel_launch(void* const* d_in, const int* in_sizes, int n_in,
                              void* d_out, int out_size) {
    (void)n_in; (void)out_size;
    const float* q;
    const float* r;
    if (in_sizes[0] < in_sizes[1]) { q = (const float*)d_in[0]; r = (const float*)d_in[1]; }
    else                           { q = (const float*)d_in[1]; r = (const float*)d_in[0]; }

    knn_p1<<<QBLK * NCHUNK, QPB>>>(q, r);
    knn_p2<<<(NQ + 127) / 128, 128>>>((float*)d_out);
}

// round 9
// speedup vs baseline: 1.3624x; 1.3624x over previous
#include <cuda_runtime.h>
#include <cstdint>

#define NQ      8192
#define NR      16384
#define KNN     8
#define NCHUNK  32
#define RPC     (NR / NCHUNK)     // 512 refs per chunk
#define PPC     (RPC / 2)         // 256 packed pairs (8 KB tile)
#define QPB     128               // threads per block
#define QT      4                 // queries per thread
#define QPG     (QPB * QT)        // 512 queries per block
#define QBLK    (NQ / QPG)        // 16 -> grid 512 for p1a/p1c
#define NSL     32                // slices per chunk
#define PPSL    (PPC / NSL)       // 8 pairs per slice (16 refs)
#define CAPP    16                // candidate-pair cap per (query, chunk)

typedef unsigned long long ull;

__device__ float      g_t2[2 * NCHUNK * NQ];               // per-chunk sorted-2 slice-minima
__device__ float      g_tau[NQ];                           // global per-query threshold
__device__ ulonglong2 g_ckey[(size_t)NQ * NCHUNK * CAPP];  // candidate pairs
__device__ int        g_cnt[NCHUNK * NQ];

__device__ __forceinline__ ull fma2(ull a, ull b, ull c) {
    ull d; asm("fma.rn.f32x2 %0, %1, %2, %3;" : "=l"(d) : "l"(a), "l"(b), "l"(c));
    return d;
}
__device__ __forceinline__ ull pk2(float lo, float hi) {
    ull r; asm("mov.b64 %0, {%1, %2};" : "=l"(r) : "f"(lo), "f"(hi));
    return r;
}
__device__ __forceinline__ void up2(float& lo, float& hi, ull v) {
    asm("mov.b64 {%0, %1}, %2;" : "=f"(lo), "=f"(hi) : "l"(v));
}
__device__ __forceinline__ unsigned f2ord(float f) {
    unsigned b = __float_as_uint(f);
    return (b & 0x80000000u) ? ~b : (b | 0x80000000u);
}

// Shared tile stage: pack {x01,y01,z01,w01}, w = r^2 with reference rounding.
__device__ __forceinline__ void stage_tile(ulonglong4* tile, const float* __restrict__ ref,
                                           int rbase) {
    for (int p = threadIdx.x; p < PPC; p += QPB) {
        const float2* a = (const float2*)(ref + (size_t)(rbase + 2 * p) * 3);
        float2 u0 = __ldg(a), u1 = __ldg(a + 1), u2 = __ldg(a + 2);
        float x0 = u0.x, y0 = u0.y, z0 = u1.x, x1 = u1.y, y1 = u2.x, z1 = u2.y;
        float w0 = __fadd_rn(__fadd_rn(__fmul_rn(x0, x0), __fmul_rn(y0, y0)), __fmul_rn(z0, z0));
        float w1 = __fadd_rn(__fadd_rn(__fmul_rn(x1, x1), __fmul_rn(y1, y1)), __fmul_rn(z1, z1));
        ulonglong4 v;
        v.x = pk2(x0, x1); v.y = pk2(y0, y1); v.z = pk2(z0, z1); v.w = pk2(w0, w1);
        tile[p] = v;
    }
}

// p1a: per (query-group, chunk): slice-minima -> per-chunk sorted-2, branchless.
__global__ __launch_bounds__(QPB) void knn_p1a(const float* __restrict__ qry,
                                               const float* __restrict__ ref) {
    __shared__ ulonglong4 tile[PPC];
    const int chunk = blockIdx.x % NCHUNK;
    const int qb    = (blockIdx.x / NCHUNK) * QPG + threadIdx.x;
    stage_tile(tile, ref, chunk * RPC);

    ull m2x[QT], m2y[QT], m2z[QT];
#pragma unroll
    for (int k = 0; k < QT; ++k) {
        int qi = qb + k * QPB;
        float qx = qry[qi * 3 + 0], qy = qry[qi * 3 + 1], qz = qry[qi * 3 + 2];
        m2x[k] = pk2(-2.0f * qx, -2.0f * qx);
        m2y[k] = pk2(-2.0f * qy, -2.0f * qy);
        m2z[k] = pk2(-2.0f * qz, -2.0f * qz);
    }
    const float INF = __int_as_float(0x7f800000);
    float t0[QT], t1[QT];
#pragma unroll
    for (int k = 0; k < QT; ++k) { t0[k] = INF; t1[k] = INF; }
    __syncthreads();

    for (int sl = 0; sl < NSL; ++sl) {
        float a0[QT], a1[QT];
#pragma unroll
        for (int k = 0; k < QT; ++k) { a0[k] = INF; a1[k] = INF; }
        const ulonglong4* base = tile + sl * PPSL;
#pragma unroll
        for (int it = 0; it < PPSL; ++it) {
            ulonglong4 v = base[it];           // warp-uniform -> LDS broadcast
#pragma unroll
            for (int k = 0; k < QT; ++k) {
                ull s2 = fma2(m2x[k], v.x, fma2(m2y[k], v.y, fma2(m2z[k], v.z, v.w)));
                float s0, s1; up2(s0, s1, s2);
                a0[k] = fminf(a0[k], s0); a1[k] = fminf(a1[k], s1);
            }
        }
#pragma unroll
        for (int k = 0; k < QT; ++k) {         // fold slice-min into sorted-2
            float m  = fminf(a0[k], a1[k]);
            float hi = fmaxf(t0[k], m);
            t0[k] = fminf(t0[k], m);
            t1[k] = fminf(t1[k], hi);
        }
    }
#pragma unroll
    for (int k = 0; k < QT; ++k) {
        int qi = qb + k * QPB;                  // coalesced (consecutive tid -> consecutive qi)
        g_t2[(chunk * 2 + 0) * NQ + qi] = t0[k];
        g_t2[(chunk * 2 + 1) * NQ + qi] = t1[k];
    }
}

// p1b: per query: fold 64 kept slice-minima -> tau* = 8th smallest.
__global__ void knn_p1b() {
    int qi = blockIdx.x * blockDim.x + threadIdx.x;
    if (qi >= NQ) return;
    const float INF = __int_as_float(0x7f800000);
    float t[KNN];
#pragma unroll
    for (int j = 0; j < KNN; ++j) t[j] = INF;
#pragma unroll 4
    for (int s = 0; s < 2 * NCHUNK; ++s) {
        float c = g_t2[s * NQ + qi];            // coalesced
#pragma unroll
        for (int j = 0; j < KNN; ++j) { float lo = fminf(t[j], c), hi = fmaxf(t[j], c); t[j] = lo; c = hi; }
    }
    g_tau[qi] = t[KNN - 1];
}

// p1c: predicated compaction of pairs with min(s0,s1) <= tau*.
__global__ __launch_bounds__(QPB) void knn_p1c(const float* __restrict__ qry,
                                               const float* __restrict__ ref) {
    __shared__ ulonglong4 tile[PPC];
    const int chunk = blockIdx.x % NCHUNK;
    const int rbase = chunk * RPC;
    const int qb    = (blockIdx.x / NCHUNK) * QPG + threadIdx.x;
    stage_tile(tile, ref, rbase);

    ull m2x[QT], m2y[QT], m2z[QT];
    float tau[QT];
    ulonglong2* buf[QT];
    int c[QT];
#pragma unroll
    for (int k = 0; k < QT; ++k) {
        int qi = qb + k * QPB;
        float qx = qry[qi * 3 + 0], qy = qry[qi * 3 + 1], qz = qry[qi * 3 + 2];
        m2x[k] = pk2(-2.0f * qx, -2.0f * qx);
        m2y[k] = pk2(-2.0f * qy, -2.0f * qy);
        m2z[k] = pk2(-2.0f * qz, -2.0f * qz);
        tau[k] = g_tau[qi];
        buf[k] = g_ckey + ((size_t)qi * NCHUNK + chunk) * CAPP;
        c[k]   = 0;
    }
    __syncthreads();

#pragma unroll 4
    for (int p = 0; p < PPC; ++p) {
        ulonglong4 v = tile[p];
        unsigned ri = (unsigned)(rbase + 2 * p);
#pragma unroll
        for (int k = 0; k < QT; ++k) {
            ull s2 = fma2(m2x[k], v.x, fma2(m2y[k], v.y, fma2(m2z[k], v.z, v.w)));
            float s0, s1; up2(s0, s1, s2);
            ull k0 = ((ull)__float_as_uint(s0) << 32) | ri;
            ull k1 = ((ull)__float_as_uint(s1) << 32) | (ri + 1);
            float smin = fminf(s0, s1);
            ulonglong2* addr = buf[k] + (c[k] < CAPP - 1 ? c[k] : CAPP - 1);
            asm volatile("{\n\t"
                         ".reg .pred p;\n\t"
                         "setp.le.f32 p, %0, %1;\n\t"
                         "@p st.global.v2.u64 [%2], {%3, %4};\n\t"
                         "}" :: "f"(smin), "f"(tau[k]), "l"(addr), "l"(k0), "l"(k1)
                         : "memory");
            c[k] += (smin <= tau[k]);
        }
    }
#pragma unroll
    for (int k = 0; k < QT; ++k)
        g_cnt[chunk * NQ + (qb + k * QPB)] = (c[k] < CAPP) ? c[k] : CAPP;
}

// p2: merge ~10 candidate pairs per query; emit top-8 indices as floats.
__global__ void knn_p2(float* __restrict__ out) {
    int qi = blockIdx.x * blockDim.x + threadIdx.x;
    if (qi >= NQ) return;

    ull best[KNN];
#pragma unroll
    for (int j = 0; j < KNN; ++j) best[j] = ~0ull;

    for (int ch = 0; ch < NCHUNK; ++ch) {
        int n = g_cnt[ch * NQ + qi];            // coalesced
        const ulonglong2* buf = g_ckey + ((size_t)qi * NCHUNK + ch) * CAPP;
        for (int j = 0; j < n; ++j) {
            ulonglong2 kp = buf[j];
#pragma unroll 2
            for (int h = 0; h < 2; ++h) {
                ull raw = h ? kp.y : kp.x;
                ull k = ((ull)f2ord(__uint_as_float((unsigned)(raw >> 32))) << 32)
                        | (raw & 0xffffffffu);
                if (k < best[KNN - 1]) {
#pragma unroll
                    for (int m = 0; m < KNN; ++m) {
                        if (k < best[m]) { ull tmp = best[m]; best[m] = k; k = tmp; }
                    }
                }
            }
        }
    }
#pragma unroll
    for (int j = 0; j < KNN; ++j)
        out[qi * KNN + j] = (float)(int)(best[j] & 0xffffffffu);
}

extern "C" void kernel_launch(void* const* d_in, const int* in_sizes, int n_in,
                              void* d_out, int out_size) {
    (void)n_in; (void)out_size;
    const float* q;
    const float* r;
    if (in_sizes[0] < in_sizes[1]) { q = (const float*)d_in[0]; r = (const float*)d_in[1]; }
    else                           { q = (const float*)d_in[1]; r = (const float*)d_in[0]; }

    knn_p1a<<<QBLK * NCHUNK, QPB>>>(q, r);
    knn_p1b<<<NQ / 128, 128>>>();
    knn_p1c<<<QBLK * NCHUNK, QPB>>>(q, r);
    knn_p2<<<NQ / 128, 128>>>((float*)d_out);
}